// round 1
// baseline (speedup 1.0000x reference)
#include <cuda_runtime.h>
#include <math.h>

#define B_ 32
#define T_ 1024
#define C_ 512
#define H_ 256

// ---------------- static device scratch (no runtime allocation) ----------------
__device__ float g_bufA[(size_t)B_ * T_ * C_];                 // 64 MB
__device__ float g_bufB[(size_t)B_ * T_ * C_];                 // 64 MB
__device__ float g_xg[(size_t)2 * B_ * T_ * 4 * H_];           // 268 MB
__device__ float g_hs[(size_t)2 * T_ * B_ * H_];               // 67 MB
__device__ unsigned int g_flags[128];

// ---------------- embedding ----------------
__global__ void embed_kernel(const int* __restrict__ x,
                             const unsigned char* __restrict__ m,
                             const float* __restrict__ emb) {
    size_t i = (size_t)blockIdx.x * blockDim.x + threadIdx.x;  // over B*T*C
    size_t bt = i / C_;
    int c = (int)(i % C_);
    int sym = x[bt];
    float v = emb[(size_t)sym * C_ + c];
    if (m[bt]) v = 0.f;
    g_bufA[i] = v;
}

// ---------------- conv / GEMM (implicit GEMM over taps) ----------------
// Out[b,t,co] = sum_{tap,ci} A[b, t+tap-(TAPS-1)/2, ci] * W[tap,ci,co] + bias[co]
// Cin fixed at 512. BM=128 (t), BN=128 (co), BK=8, 256 threads, 8x8 microtile.
template <int TAPS>
__global__ __launch_bounds__(256) void gemm_conv_kernel(
    const float* __restrict__ A, const float* __restrict__ W,
    const float* __restrict__ bias, float* __restrict__ Out, int Cout) {
    __shared__ float As[8][132];   // [ci][t], padded
    __shared__ float Bs[8][128];   // [ci][co]

    const int tid = threadIdx.x;
    const int bb = blockIdx.x >> 3;
    const int t0 = (blockIdx.x & 7) * 128;
    const int co0 = blockIdx.y * 128;
    const int tx = tid & 15;
    const int ty = tid >> 4;

    float acc[8][8];
#pragma unroll
    for (int i = 0; i < 8; i++)
#pragma unroll
        for (int j = 0; j < 8; j++) acc[i][j] = 0.f;

    const int arow = tid >> 1;          // 0..127 (t within tile)
    const int aci4 = (tid & 1) * 4;     // 0 or 4
    const int brow = tid >> 5;          // 0..7 (ci within tile)
    const int bco4 = (tid & 31) * 4;    // 0..124

    const int tileCount = TAPS * 64;    // 64 = 512/8
    const int half = (TAPS - 1) / 2;

    float4 aN, bN;
    {
        const int tap = 0, kt = 0;
        int tsrc = t0 + arow + tap - half;
        bool ok = ((unsigned)tsrc < (unsigned)T_);
        aN = ok ? *(const float4*)(A + ((size_t)bb * T_ + tsrc) * C_ + kt * 8 + aci4)
                : make_float4(0.f, 0.f, 0.f, 0.f);
        bN = *(const float4*)(W + ((size_t)(tap * 512 + kt * 8 + brow)) * Cout + co0 + bco4);
    }

    for (int tile = 0; tile < tileCount; tile++) {
        As[aci4 + 0][arow] = aN.x;
        As[aci4 + 1][arow] = aN.y;
        As[aci4 + 2][arow] = aN.z;
        As[aci4 + 3][arow] = aN.w;
        *(float4*)&Bs[brow][bco4] = bN;
        __syncthreads();

        if (tile + 1 < tileCount) {
            const int nt = tile + 1;
            const int tap = nt >> 6;
            const int kt = nt & 63;
            int tsrc = t0 + arow + tap - half;
            bool ok = ((unsigned)tsrc < (unsigned)T_);
            aN = ok ? *(const float4*)(A + ((size_t)bb * T_ + tsrc) * C_ + kt * 8 + aci4)
                    : make_float4(0.f, 0.f, 0.f, 0.f);
            bN = *(const float4*)(W + ((size_t)(tap * 512 + kt * 8 + brow)) * Cout + co0 + bco4);
        }

#pragma unroll
        for (int kk = 0; kk < 8; kk++) {
            float a8[8], b8[8];
            *(float4*)(a8 + 0) = *(const float4*)&As[kk][ty * 8 + 0];
            *(float4*)(a8 + 4) = *(const float4*)&As[kk][ty * 8 + 4];
            *(float4*)(b8 + 0) = *(const float4*)&Bs[kk][tx * 8 + 0];
            *(float4*)(b8 + 4) = *(const float4*)&Bs[kk][tx * 8 + 4];
#pragma unroll
            for (int i = 0; i < 8; i++)
#pragma unroll
                for (int j = 0; j < 8; j++) acc[i][j] += a8[i] * b8[j];
        }
        __syncthreads();
    }

#pragma unroll
    for (int i = 0; i < 8; i++) {
        int t = t0 + ty * 8 + i;
        float* orow = Out + ((size_t)bb * T_ + t) * Cout + co0 + tx * 8;
#pragma unroll
        for (int j = 0; j < 8; j++) orow[j] = acc[i][j] + bias[co0 + tx * 8 + j];
    }
}

// ---------------- LayerNorm over time + leaky relu + mask (in place) ----------------
__global__ void ln_lrelu_kernel(float* __restrict__ h,
                                const float* __restrict__ scale,
                                const float* __restrict__ bias,
                                const unsigned char* __restrict__ m) {
    const int b = blockIdx.x;
    const int c = blockIdx.y * 128 + threadIdx.x;
    float* hb = h + (size_t)b * T_ * C_ + c;
    float s = 0.f, s2 = 0.f;
#pragma unroll 8
    for (int t = 0; t < T_; t++) {
        float v = hb[(size_t)t * C_];
        s += v;
        s2 += v * v;
    }
    const float mu = s * (1.f / T_);
    const float var = s2 * (1.f / T_) - mu * mu;
    const float rs = rsqrtf(var + 1e-5f);
    const unsigned char* mb = m + (size_t)b * T_;
#pragma unroll 4
    for (int t = 0; t < T_; t++) {
        float v = hb[(size_t)t * C_];
        v = (v - mu) * rs * scale[t] + bias[t];
        v = (v > 0.f) ? v : 0.2f * v;
        if (mb[t]) v = 0.f;
        hb[(size_t)t * C_] = v;
    }
}

// ---------------- flag reset (graph-replay safe) ----------------
__global__ void reset_flags_kernel() {
    if (threadIdx.x < 128) g_flags[threadIdx.x] = 0;
}

// ---------------- bidirectional LSTM recurrence ----------------
// Grid: 128 CTAs = dir(2) x batch-group(8, 4 batches each) x h-group(8, 32 units each)
// Each CTA keeps its wh slice [256 x 128 gate-cols] in SMEM; per-step hidden-state
// exchange via global g_hs + release/acquire flag spin. All CTAs co-resident.
__global__ __launch_bounds__(512) void lstm_kernel(const float* __restrict__ wh_fw,
                                                   const float* __restrict__ wh_bw) {
    extern __shared__ float sm[];
    float* whs = sm;                 // [128][260] column-major per gate-col, padded
    float* hps = whs + 128 * 260;    // [4][256] previous hidden for 4 batches
    float* gbuf = hps + 4 * 256;     // [128 gatecols][4 batches]
    float* cbuf = gbuf + 512;        // [4][32] cell state

    const int tid = threadIdx.x;
    const int dir = blockIdx.x >> 6;
    const int bg = (blockIdx.x >> 3) & 7;
    const int hg = blockIdx.x & 7;
    const int u0 = hg * 32;
    const int b0 = bg * 4;

    const float* wh = dir ? wh_bw : wh_fw;
    // load wh slice: whs[g][k] where gate-col g = q*32+j maps to global col q*256+u0+j
    for (int i = tid; i < 256 * 128; i += 512) {
        int k = i >> 7;
        int gg = i & 127;
        int q = gg >> 5, j = gg & 31;
        whs[gg * 260 + k] = wh[(size_t)k * 1024 + q * 256 + u0 + j];
    }
    for (int i = tid; i < 1024; i += 512) hps[i] = 0.f;
    if (tid < 128) cbuf[tid] = 0.f;
    __syncthreads();

    const int g = tid & 127;         // gate-col within slice
    const int bl = tid >> 7;         // local batch 0..3
    const int q = g >> 5;
    const int j = g & 31;
    const int col = q * 256 + u0 + j;

    const float* xgd = g_xg + (size_t)dir * B_ * T_ * 1024;
    float* hsd = g_hs + (size_t)dir * T_ * B_ * H_;
    volatile unsigned int* flg = (volatile unsigned int*)(g_flags + dir * 64 + bg * 8);

    for (int s = 0; s < T_; s++) {
        const int t = dir ? (T_ - 1 - s) : s;
        // issue xg load early (independent of the flag wait)
        float xv = xgd[((size_t)(b0 + bl) * T_ + t) * 1024 + col];

        if (s > 0) {
            if (tid < 8) {
                while (flg[tid] < (unsigned)s) { }
            }
            __syncthreads();
            const int tprev = dir ? (t + 1) : (t - 1);
            const float* src = hsd + ((size_t)tprev * B_ + b0) * H_;  // 4 KB contiguous
            for (int i = tid; i < 1024; i += 512) hps[i] = __ldcg(src + i);
        }
        __syncthreads();

        // gate dot product: acc = xv + sum_k whs[g][k] * hp[bl][k]
        float acc = xv;
        const float* wcol = whs + g * 260;
        const float* hrow = hps + bl * 256;
#pragma unroll
        for (int k = 0; k < 256; k += 4) {
            float4 w4 = *(const float4*)(wcol + k);
            float4 h4 = *(const float4*)(hrow + k);
            acc += w4.x * h4.x;
            acc += w4.y * h4.y;
            acc += w4.z * h4.z;
            acc += w4.w * h4.w;
        }
        float a = (q == 2) ? tanhf(acc) : (1.f / (1.f + expf(-acc)));
        gbuf[g * 4 + bl] = a;
        __syncthreads();

        if (tid < 128) {
            const int u = tid & 31;
            const int bi = tid >> 5;
            float iv = gbuf[(u) * 4 + bi];
            float fv = gbuf[(32 + u) * 4 + bi];
            float gv = gbuf[(64 + u) * 4 + bi];
            float ov = gbuf[(96 + u) * 4 + bi];
            float c = fv * cbuf[bi * 32 + u] + iv * gv;
            cbuf[bi * 32 + u] = c;
            float hn = ov * tanhf(c);
            hsd[((size_t)t * B_ + b0 + bi) * H_ + u0 + u] = hn;
            __threadfence();
        }
        __syncthreads();
        if (tid == 0) flg[hg] = (unsigned)(s + 1);
    }
}

// ---------------- output transpose [2][T][B][H] -> [B, 2H, T] ----------------
__global__ void out_kernel(float* __restrict__ out, const unsigned char* __restrict__ m) {
    const int dir = blockIdx.y >> 3;
    const int h0 = (blockIdx.y & 7) * 32;
    const int t0 = blockIdx.x * 32;
    const int b = blockIdx.z;
    __shared__ float tile[32][33];
    const float* hsd = g_hs + (size_t)dir * T_ * B_ * H_;
    const int tx = threadIdx.x, ty = threadIdx.y;
#pragma unroll
    for (int r = 0; r < 32; r += 8) {
        int t = t0 + ty + r;
        tile[ty + r][tx] = hsd[((size_t)t * B_ + b) * H_ + h0 + tx];
    }
    __syncthreads();
#pragma unroll
    for (int r = 0; r < 32; r += 8) {
        int hh = ty + r;
        int c = dir * H_ + h0 + hh;
        int t = t0 + tx;
        float v = tile[tx][hh];
        if (m[(size_t)b * T_ + t]) v = 0.f;
        out[((size_t)b * C_ + c) * T_ + t] = v;
    }
}

// ---------------- launch ----------------
extern "C" void kernel_launch(void* const* d_in, const int* in_sizes, int n_in,
                              void* d_out, int out_size) {
    const int* x = (const int*)d_in[0];
    // d_in[1] = input_lengths (unused; padding comes from the mask)
    const unsigned char* m = (const unsigned char*)d_in[2];
    const float* emb = (const float*)d_in[3];
    const float* conv_w = (const float*)d_in[4];
    const float* conv_b = (const float*)d_in[5];
    const float* ln_scale = (const float*)d_in[6];
    const float* ln_bias = (const float*)d_in[7];
    const float* wx_fw = (const float*)d_in[8];
    const float* wh_fw = (const float*)d_in[9];
    const float* b_fw = (const float*)d_in[10];
    const float* wx_bw = (const float*)d_in[11];
    const float* wh_bw = (const float*)d_in[12];
    const float* b_bw = (const float*)d_in[13];
    float* out = (float*)d_out;

    float *bufA, *bufB, *xg;
    cudaGetSymbolAddress((void**)&bufA, g_bufA);
    cudaGetSymbolAddress((void**)&bufB, g_bufB);
    cudaGetSymbolAddress((void**)&xg, g_xg);

    // 1) embedding
    embed_kernel<<<(int)(((size_t)B_ * T_ * C_) / 256), 256>>>(x, m, emb);

    // 2) conv stack
    float* cur = bufA;
    float* nxt = bufB;
    for (int d = 0; d < 3; d++) {
        gemm_conv_kernel<5><<<dim3(B_ * 8, 4), 256>>>(
            cur, conv_w + (size_t)d * 5 * 512 * 512, conv_b + (size_t)d * 512, nxt, 512);
        ln_lrelu_kernel<<<dim3(B_, 4), 128>>>(nxt, ln_scale + (size_t)d * T_,
                                              ln_bias + (size_t)d * T_, m);
        float* tmp = cur; cur = nxt; nxt = tmp;
    }
    // cur now holds final conv activations

    // 3) LSTM input projections (gates precompute), bias fused
    gemm_conv_kernel<1><<<dim3(B_ * 8, 8), 256>>>(cur, wx_fw, b_fw, xg, 1024);
    gemm_conv_kernel<1><<<dim3(B_ * 8, 8), 256>>>(cur, wx_bw, b_bw,
                                                  xg + (size_t)B_ * T_ * 1024, 1024);

    // 4) recurrence
    reset_flags_kernel<<<1, 128>>>();
    const int lstm_smem = (128 * 260 + 4 * 256 + 512 + 128) * 4;  // 139776 B
    cudaFuncSetAttribute(lstm_kernel, cudaFuncAttributeMaxDynamicSharedMemorySize, lstm_smem);
    lstm_kernel<<<128, 512, lstm_smem>>>(wh_fw, wh_bw);

    // 5) concat + transpose + mask -> d_out [B, C, T]
    out_kernel<<<dim3(T_ / 32, 16, B_), dim3(32, 8)>>>(out, m);
}

// round 3
// speedup vs baseline: 1.7481x; 1.7481x over previous
#include <cuda_runtime.h>
#include <math.h>
#include <stdint.h>

#define B_ 32
#define T_ 1024
#define C_ 512
#define H_ 256

// ---------------- static device scratch ----------------
__device__ float g_bufA[(size_t)B_ * T_ * C_];
__device__ float g_bufB[(size_t)B_ * T_ * C_];
__device__ float g_xg[(size_t)2 * B_ * T_ * 4 * H_];
__device__ float g_hs[(size_t)2 * T_ * B_ * H_];
__device__ float g_wT[(size_t)3 * 5 * 512 * 512];   // conv W transposed [d][tap][co][ci]
__device__ float g_wxT[(size_t)2 * 1024 * 512];     // wx transposed [dir][gatecol][ci]
__device__ unsigned int g_flags[128];

// ---------------- helpers ----------------
__device__ __forceinline__ float tf32r(float x) {
    uint32_t u; asm("cvt.rna.tf32.f32 %0, %1;" : "=r"(u) : "f"(x));
    return __uint_as_float(u);
}
__device__ __forceinline__ uint32_t smem_u32(const void* p) {
    uint32_t a;
    asm("{ .reg .u64 t; cvta.to.shared.u64 t, %1; cvt.u32.u64 %0, t; }" : "=r"(a) : "l"(p));
    return a;
}
__device__ __forceinline__ void cp16(uint32_t dst, const void* src, int srcsz) {
    asm volatile("cp.async.cg.shared.global [%0], [%1], 16, %2;"
                 :: "r"(dst), "l"(src), "r"(srcsz));
}
#define CP_COMMIT() asm volatile("cp.async.commit_group;")
#define CP_WAIT1()  asm volatile("cp.async.wait_group 1;")

__device__ __forceinline__ void mma_tf32(float& c0, float& c1, float& c2, float& c3,
                                         uint32_t a0, uint32_t a1, uint32_t a2, uint32_t a3,
                                         uint32_t b0, uint32_t b1) {
    asm volatile(
        "mma.sync.aligned.m16n8k8.row.col.f32.tf32.tf32.f32 "
        "{%0,%1,%2,%3}, {%4,%5,%6,%7}, {%8,%9}, {%0,%1,%2,%3};"
        : "+f"(c0), "+f"(c1), "+f"(c2), "+f"(c3)
        : "r"(a0), "r"(a1), "r"(a2), "r"(a3), "r"(b0), "r"(b1));
}

// ---------------- weight transpose + tf32 round ----------------
__global__ void transpose_round_kernel(const float* __restrict__ src, float* __restrict__ dst,
                                       int R, int Cc) {
    __shared__ float t[32][33];
    const size_t slab = (size_t)R * Cc;
    const float* s = src + (size_t)blockIdx.z * slab;
    float* d = dst + (size_t)blockIdx.z * slab;
    int c0 = blockIdx.x * 32, r0 = blockIdx.y * 32;
    int x = threadIdx.x, y = threadIdx.y;
#pragma unroll
    for (int i = y; i < 32; i += 8)
        t[i][x] = s[(size_t)(r0 + i) * Cc + c0 + x];
    __syncthreads();
#pragma unroll
    for (int i = y; i < 32; i += 8)
        d[(size_t)(c0 + i) * R + r0 + x] = tf32r(t[x][i]);
}

// ---------------- embedding (tf32-rounded) ----------------
__global__ void embed_kernel(const int* __restrict__ x,
                             const unsigned char* __restrict__ m,
                             const float* __restrict__ emb) {
    size_t i = (size_t)blockIdx.x * blockDim.x + threadIdx.x;
    size_t bt = i / C_;
    int c = (int)(i % C_);
    int sym = x[bt];
    float v = emb[(size_t)sym * C_ + c];
    if (m[bt]) v = 0.f;
    g_bufA[i] = tf32r(v);
}

// ---------------- tf32 mma.sync GEMM / implicit conv ----------------
// Out[b,t,co] = sum_{tap,ci} A[b,t+tap-half,ci] * WT[tap,co,ci] + bias[co]
// Block 128x128, BK=16, 256 threads (8 warps 2x4, warp tile 64x32).
// Smem tiles stored [row][k] with stride 20 floats (conflict-free fragment loads).
#define LDK 20
template <int TAPS>
__global__ __launch_bounds__(256) void mma_gemm_kernel(
    const float* __restrict__ A, const float* __restrict__ WT,
    const float* __restrict__ bias, float* __restrict__ Out, int Cout) {
    __shared__ uint32_t As[2][128 * LDK];
    __shared__ uint32_t Bs[2][128 * LDK];

    const int tid = threadIdx.x;
    const int wid = tid >> 5, lane = tid & 31;
    const int r = lane >> 2, cq = lane & 3;
    const int warp_m = wid & 1, warp_n = wid >> 1;
    const int m0 = warp_m * 64, n0 = warp_n * 32;

    const int bb = blockIdx.x >> 3;
    const int t0 = (blockIdx.x & 7) * 128;
    const int co0 = blockIdx.y * 128;
    const int NT = TAPS * 32;
    const int half = (TAPS - 1) / 2;

    float acc[4][4][4];
#pragma unroll
    for (int i = 0; i < 4; i++)
#pragma unroll
        for (int j = 0; j < 4; j++)
#pragma unroll
            for (int k = 0; k < 4; k++) acc[i][j][k] = 0.f;

    const uint32_t asb[2] = { smem_u32(&As[0][0]), smem_u32(&As[1][0]) };
    const uint32_t bsb[2] = { smem_u32(&Bs[0][0]), smem_u32(&Bs[1][0]) };

    // each thread loads 2 A-chunks + 2 B-chunks of 16B per tile
    auto load_tile = [&](int tidx, int stage) {
        const int tap = (TAPS == 1) ? 0 : (tidx >> 5);
        const int kt = (TAPS == 1) ? tidx : (tidx & 31);
        const float* Ab = A + (size_t)bb * T_ * C_ + kt * 16;
#pragma unroll
        for (int it = 0; it < 2; it++) {
            int chunk = it * 256 + tid;
            int row = chunk >> 2, seg = chunk & 3;
            int t = t0 + row + tap - half;
            int ok = ((unsigned)t < (unsigned)T_) ? 16 : 0;
            int tc = t < 0 ? 0 : (t > T_ - 1 ? T_ - 1 : t);
            cp16(asb[stage] + (row * LDK + seg * 4) * 4, Ab + (size_t)tc * C_ + seg * 4, ok);
        }
        const float* Bb = WT + ((size_t)tap * Cout + co0) * C_ + kt * 16;
#pragma unroll
        for (int it = 0; it < 2; it++) {
            int chunk = it * 256 + tid;
            int row = chunk >> 2, seg = chunk & 3;
            cp16(bsb[stage] + (row * LDK + seg * 4) * 4, Bb + (size_t)row * C_ + seg * 4, 16);
        }
    };

    load_tile(0, 0);
    CP_COMMIT();

    for (int t = 0; t < NT; t++) {
        const int cur = t & 1;
        if (t + 1 < NT) load_tile(t + 1, (t + 1) & 1);
        CP_COMMIT();
        CP_WAIT1();
        __syncthreads();

        const uint32_t* Ac = As[cur];
        const uint32_t* Bc = Bs[cur];
#pragma unroll
        for (int ks = 0; ks < 2; ks++) {
            const int k0 = ks * 8;
            uint32_t af[4][4], bf[4][2];
#pragma unroll
            for (int i = 0; i < 4; i++) {
                const uint32_t* p = Ac + (m0 + i * 16 + r) * LDK + k0 + cq;
                af[i][0] = p[0];
                af[i][1] = p[8 * LDK];
                af[i][2] = p[4];
                af[i][3] = p[8 * LDK + 4];
            }
#pragma unroll
            for (int j = 0; j < 4; j++) {
                const uint32_t* p = Bc + (n0 + j * 8 + r) * LDK + k0 + cq;
                bf[j][0] = p[0];
                bf[j][1] = p[4];
            }
#pragma unroll
            for (int i = 0; i < 4; i++)
#pragma unroll
                for (int j = 0; j < 4; j++)
                    mma_tf32(acc[i][j][0], acc[i][j][1], acc[i][j][2], acc[i][j][3],
                             af[i][0], af[i][1], af[i][2], af[i][3], bf[j][0], bf[j][1]);
        }
        __syncthreads();
    }

    // epilogue: direct stores (float2), bias fused
#pragma unroll
    for (int j = 0; j < 4; j++) {
        const int col = co0 + n0 + j * 8 + 2 * cq;
        const float bv0 = bias[col], bv1 = bias[col + 1];
#pragma unroll
        for (int i = 0; i < 4; i++) {
            int row = t0 + m0 + i * 16 + r;
            float2 v0 = make_float2(acc[i][j][0] + bv0, acc[i][j][1] + bv1);
            float2 v1 = make_float2(acc[i][j][2] + bv0, acc[i][j][3] + bv1);
            *(float2*)(Out + ((size_t)bb * T_ + row) * Cout + col) = v0;
            *(float2*)(Out + ((size_t)bb * T_ + row + 8) * Cout + col) = v1;
        }
    }
}

// ---------------- LayerNorm over time + leaky relu + mask (tf32-rounded out) ----------------
__global__ void ln_lrelu_kernel(float* __restrict__ h,
                                const float* __restrict__ scale,
                                const float* __restrict__ bias,
                                const unsigned char* __restrict__ m) {
    const int b = blockIdx.x;
    const int c = blockIdx.y * 128 + threadIdx.x;
    float* hb = h + (size_t)b * T_ * C_ + c;
    float s = 0.f, s2 = 0.f;
#pragma unroll 8
    for (int t = 0; t < T_; t++) {
        float v = hb[(size_t)t * C_];
        s += v; s2 += v * v;
    }
    const float mu = s * (1.f / T_);
    const float var = s2 * (1.f / T_) - mu * mu;
    const float rs = rsqrtf(var + 1e-5f);
    const unsigned char* mb = m + (size_t)b * T_;
#pragma unroll 4
    for (int t = 0; t < T_; t++) {
        float v = hb[(size_t)t * C_];
        v = (v - mu) * rs * scale[t] + bias[t];
        v = (v > 0.f) ? v : 0.2f * v;
        if (mb[t]) v = 0.f;
        hb[(size_t)t * C_] = tf32r(v);
    }
}

// ---------------- flag reset ----------------
__global__ void reset_flags_kernel() {
    if (threadIdx.x < 128) g_flags[threadIdx.x] = 0;
}

// ---------------- bidirectional LSTM recurrence ----------------
__global__ __launch_bounds__(512) void lstm_kernel(const float* __restrict__ wh_fw,
                                                   const float* __restrict__ wh_bw) {
    extern __shared__ float sm[];
    float* whs = sm;
    float* hps = whs + 128 * 260;
    float* gbuf = hps + 4 * 256;
    float* cbuf = gbuf + 512;

    const int tid = threadIdx.x;
    const int dir = blockIdx.x >> 6;
    const int bg = (blockIdx.x >> 3) & 7;
    const int hg = blockIdx.x & 7;
    const int u0 = hg * 32;
    const int b0 = bg * 4;

    const float* wh = dir ? wh_bw : wh_fw;
    for (int i = tid; i < 256 * 128; i += 512) {
        int k = i >> 7;
        int gg = i & 127;
        int q = gg >> 5, j = gg & 31;
        whs[gg * 260 + k] = wh[(size_t)k * 1024 + q * 256 + u0 + j];
    }
    for (int i = tid; i < 1024; i += 512) hps[i] = 0.f;
    if (tid < 128) cbuf[tid] = 0.f;
    __syncthreads();

    const int g = tid & 127;
    const int bl = tid >> 7;
    const int q = g >> 5;
    const int j = g & 31;
    const int col = q * 256 + u0 + j;

    const float* xgd = g_xg + (size_t)dir * B_ * T_ * 1024;
    float* hsd = g_hs + (size_t)dir * T_ * B_ * H_;
    volatile unsigned int* flg = (volatile unsigned int*)(g_flags + dir * 64 + bg * 8);

    for (int s = 0; s < T_; s++) {
        const int t = dir ? (T_ - 1 - s) : s;
        float xv = xgd[((size_t)(b0 + bl) * T_ + t) * 1024 + col];

        if (s > 0) {
            if (tid < 8) {
                while (flg[tid] < (unsigned)s) { }
            }
            __syncthreads();
            const int tprev = dir ? (t + 1) : (t - 1);
            const float* src = hsd + ((size_t)tprev * B_ + b0) * H_;
            for (int i = tid; i < 1024; i += 512) hps[i] = __ldcg(src + i);
        }
        __syncthreads();

        float acc = xv;
        const float* wcol = whs + g * 260;
        const float* hrow = hps + bl * 256;
#pragma unroll
        for (int k = 0; k < 256; k += 4) {
            float4 w4 = *(const float4*)(wcol + k);
            float4 h4 = *(const float4*)(hrow + k);
            acc += w4.x * h4.x;
            acc += w4.y * h4.y;
            acc += w4.z * h4.z;
            acc += w4.w * h4.w;
        }
        float a = (q == 2) ? tanhf(acc) : (1.f / (1.f + expf(-acc)));
        gbuf[g * 4 + bl] = a;
        __syncthreads();

        if (tid < 128) {
            const int u = tid & 31;
            const int bi = tid >> 5;
            float iv = gbuf[(u)*4 + bi];
            float fv = gbuf[(32 + u) * 4 + bi];
            float gv = gbuf[(64 + u) * 4 + bi];
            float ov = gbuf[(96 + u) * 4 + bi];
            float cc = fv * cbuf[bi * 32 + u] + iv * gv;
            cbuf[bi * 32 + u] = cc;
            float hn = ov * tanhf(cc);
            hsd[((size_t)t * B_ + b0 + bi) * H_ + u0 + u] = hn;
            __threadfence();
        }
        __syncthreads();
        if (tid == 0) flg[hg] = (unsigned)(s + 1);
    }
}

// ---------------- output transpose [2][T][B][H] -> [B, 2H, T] ----------------
__global__ void out_kernel(float* __restrict__ out, const unsigned char* __restrict__ m) {
    const int dir = blockIdx.y >> 3;
    const int h0 = (blockIdx.y & 7) * 32;
    const int t0 = blockIdx.x * 32;
    const int b = blockIdx.z;
    __shared__ float tile[32][33];
    const float* hsd = g_hs + (size_t)dir * T_ * B_ * H_;
    const int tx = threadIdx.x, ty = threadIdx.y;
#pragma unroll
    for (int r = 0; r < 32; r += 8) {
        int t = t0 + ty + r;
        tile[ty + r][tx] = hsd[((size_t)t * B_ + b) * H_ + h0 + tx];
    }
    __syncthreads();
#pragma unroll
    for (int r = 0; r < 32; r += 8) {
        int hh = ty + r;
        int c = dir * H_ + h0 + hh;
        int t = t0 + tx;
        float v = tile[tx][hh];
        if (m[(size_t)b * T_ + t]) v = 0.f;
        out[((size_t)b * C_ + c) * T_ + t] = v;
    }
}

// ---------------- launch ----------------
extern "C" void kernel_launch(void* const* d_in, const int* in_sizes, int n_in,
                              void* d_out, int out_size) {
    const int* x = (const int*)d_in[0];
    const unsigned char* m = (const unsigned char*)d_in[2];
    const float* emb = (const float*)d_in[3];
    const float* conv_w = (const float*)d_in[4];
    const float* conv_b = (const float*)d_in[5];
    const float* ln_scale = (const float*)d_in[6];
    const float* ln_bias = (const float*)d_in[7];
    const float* wx_fw = (const float*)d_in[8];
    const float* wh_fw = (const float*)d_in[9];
    const float* b_fw = (const float*)d_in[10];
    const float* wx_bw = (const float*)d_in[11];
    const float* wh_bw = (const float*)d_in[12];
    const float* b_bw = (const float*)d_in[13];
    float* out = (float*)d_out;

    float *bufA, *bufB, *xg, *wT, *wxT;
    cudaGetSymbolAddress((void**)&bufA, g_bufA);
    cudaGetSymbolAddress((void**)&bufB, g_bufB);
    cudaGetSymbolAddress((void**)&xg, g_xg);
    cudaGetSymbolAddress((void**)&wT, g_wT);
    cudaGetSymbolAddress((void**)&wxT, g_wxT);

    // 0) weight prep: transpose to K-major + tf32 RNA round
    transpose_round_kernel<<<dim3(16, 16, 15), dim3(32, 8)>>>(conv_w, wT, 512, 512);
    transpose_round_kernel<<<dim3(32, 16, 1), dim3(32, 8)>>>(wx_fw, wxT, 512, 1024);
    transpose_round_kernel<<<dim3(32, 16, 1), dim3(32, 8)>>>(wx_bw, wxT + (size_t)1024 * 512, 512, 1024);

    // 1) embedding (tf32-rounded)
    embed_kernel<<<(int)(((size_t)B_ * T_ * C_) / 256), 256>>>(x, m, emb);

    // 2) conv stack via tf32 mma.sync implicit GEMM
    float* cur = bufA;
    float* nxt = bufB;
    for (int d = 0; d < 3; d++) {
        mma_gemm_kernel<5><<<dim3(B_ * 8, 4), 256>>>(
            cur, wT + (size_t)d * 5 * 512 * 512, conv_b + (size_t)d * 512, nxt, 512);
        ln_lrelu_kernel<<<dim3(B_, 4), 128>>>(nxt, ln_scale + (size_t)d * T_,
                                              ln_bias + (size_t)d * T_, m);
        float* tmp = cur; cur = nxt; nxt = tmp;
    }

    // 3) LSTM input projections (bias fused)
    mma_gemm_kernel<1><<<dim3(B_ * 8, 8), 256>>>(cur, wxT, b_fw, xg, 1024);
    mma_gemm_kernel<1><<<dim3(B_ * 8, 8), 256>>>(
        cur, wxT + (size_t)1024 * 512, b_bw, xg + (size_t)B_ * T_ * 1024, 1024);

    // 4) recurrence
    reset_flags_kernel<<<1, 128>>>();
    const int lstm_smem = (128 * 260 + 4 * 256 + 512 + 128) * 4;
    cudaFuncSetAttribute(lstm_kernel, cudaFuncAttributeMaxDynamicSharedMemorySize, lstm_smem);
    lstm_kernel<<<128, 512, lstm_smem>>>(wh_fw, wh_bw);

    // 5) concat + transpose + mask -> d_out [B, C, T]
    out_kernel<<<dim3(T_ / 32, 16, B_), dim3(32, 8)>>>(out, m);
}

// round 4
// speedup vs baseline: 2.3460x; 1.3420x over previous
#include <cuda_runtime.h>
#include <math.h>
#include <stdint.h>

#define B_ 32
#define T_ 1024
#define C_ 512
#define H_ 256

// ---------------- static device scratch ----------------
__device__ float g_bufA[(size_t)B_ * T_ * C_];
__device__ float g_bufB[(size_t)B_ * T_ * C_];
__device__ float g_xg[(size_t)2 * B_ * T_ * 4 * H_];
__device__ float g_hs[(size_t)2 * T_ * B_ * H_];
__device__ float g_wT[(size_t)3 * 5 * 512 * 512];   // conv W transposed [d][tap][co][ci]
__device__ float g_wxT[(size_t)2 * 1024 * 512];     // wx transposed [dir][gatecol][ci]
__device__ unsigned int g_flags[128];

// ---------------- helpers ----------------
__device__ __forceinline__ float tf32r(float x) {
    uint32_t u; asm("cvt.rna.tf32.f32 %0, %1;" : "=r"(u) : "f"(x));
    return __uint_as_float(u);
}
__device__ __forceinline__ uint32_t smem_u32(const void* p) {
    uint32_t a;
    asm("{ .reg .u64 t; cvta.to.shared.u64 t, %1; cvt.u32.u64 %0, t; }" : "=r"(a) : "l"(p));
    return a;
}
__device__ __forceinline__ void cp16(uint32_t dst, const void* src, int srcsz) {
    asm volatile("cp.async.cg.shared.global [%0], [%1], 16, %2;"
                 :: "r"(dst), "l"(src), "r"(srcsz));
}
#define CP_COMMIT() asm volatile("cp.async.commit_group;")
#define CP_WAIT2()  asm volatile("cp.async.wait_group 2;")

__device__ __forceinline__ void mma_tf32(float& c0, float& c1, float& c2, float& c3,
                                         uint32_t a0, uint32_t a1, uint32_t a2, uint32_t a3,
                                         uint32_t b0, uint32_t b1) {
    asm volatile(
        "mma.sync.aligned.m16n8k8.row.col.f32.tf32.tf32.f32 "
        "{%0,%1,%2,%3}, {%4,%5,%6,%7}, {%8,%9}, {%0,%1,%2,%3};"
        : "+f"(c0), "+f"(c1), "+f"(c2), "+f"(c3)
        : "r"(a0), "r"(a1), "r"(a2), "r"(a3), "r"(b0), "r"(b1));
}

// ---------------- weight transpose + tf32 round ----------------
__global__ void transpose_round_kernel(const float* __restrict__ src, float* __restrict__ dst,
                                       int R, int Cc) {
    __shared__ float t[32][33];
    const size_t slab = (size_t)R * Cc;
    const float* s = src + (size_t)blockIdx.z * slab;
    float* d = dst + (size_t)blockIdx.z * slab;
    int c0 = blockIdx.x * 32, r0 = blockIdx.y * 32;
    int x = threadIdx.x, y = threadIdx.y;
#pragma unroll
    for (int i = y; i < 32; i += 8)
        t[i][x] = s[(size_t)(r0 + i) * Cc + c0 + x];
    __syncthreads();
#pragma unroll
    for (int i = y; i < 32; i += 8)
        d[(size_t)(c0 + i) * R + r0 + x] = tf32r(t[x][i]);
}

// ---------------- embedding (tf32-rounded) ----------------
__global__ void embed_kernel(const int* __restrict__ x,
                             const unsigned char* __restrict__ m,
                             const float* __restrict__ emb) {
    size_t i = (size_t)blockIdx.x * blockDim.x + threadIdx.x;
    size_t bt = i / C_;
    int c = (int)(i % C_);
    int sym = x[bt];
    float v = emb[(size_t)sym * C_ + c];
    if (m[bt]) v = 0.f;
    g_bufA[i] = tf32r(v);
}

// ---------------- tf32 mma.sync GEMM / implicit conv (4-stage pipeline) ----------------
// Out[b,t,co] = sum_{tap,ci} A[b,t+tap-half,ci] * WT[tap,co,ci] + bias[co]
// Block 128x128, BK=16, 256 threads (8 warps 2x4, warp tile 64x32).
#define LDK 20
#define TILE_U32 (128 * LDK)         // one operand tile in uint32
#define STAGE_U32 (2 * TILE_U32)     // A + B
#define NSTG 4
#define GEMM_SMEM (NSTG * STAGE_U32 * 4)

template <int TAPS>
__global__ __launch_bounds__(256) void mma_gemm_kernel(
    const float* __restrict__ A, const float* __restrict__ WT,
    const float* __restrict__ bias, float* __restrict__ Out, int Cout) {
    extern __shared__ uint32_t sh[];

    const int tid = threadIdx.x;
    const int wid = tid >> 5, lane = tid & 31;
    const int r = lane >> 2, cq = lane & 3;
    const int warp_m = wid & 1, warp_n = wid >> 1;
    const int m0 = warp_m * 64, n0 = warp_n * 32;

    const int bb = blockIdx.x >> 3;
    const int t0 = (blockIdx.x & 7) * 128;
    const int co0 = blockIdx.y * 128;
    const int NT = TAPS * 32;
    const int half = (TAPS - 1) / 2;

    float acc[4][4][4];
#pragma unroll
    for (int i = 0; i < 4; i++)
#pragma unroll
        for (int j = 0; j < 4; j++)
#pragma unroll
            for (int k = 0; k < 4; k++) acc[i][j][k] = 0.f;

    const uint32_t shb = smem_u32(sh);

    auto load_tile = [&](int tidx, int stage) {
        const uint32_t sbase = shb + stage * (STAGE_U32 * 4);
        const int tap = (TAPS == 1) ? 0 : (tidx >> 5);
        const int kt = (TAPS == 1) ? tidx : (tidx & 31);
        const float* Ab = A + (size_t)bb * T_ * C_ + kt * 16;
#pragma unroll
        for (int it = 0; it < 2; it++) {
            int chunk = it * 256 + tid;
            int row = chunk >> 2, seg = chunk & 3;
            int t = t0 + row + tap - half;
            int ok = ((unsigned)t < (unsigned)T_) ? 16 : 0;
            int tc = t < 0 ? 0 : (t > T_ - 1 ? T_ - 1 : t);
            cp16(sbase + (row * LDK + seg * 4) * 4, Ab + (size_t)tc * C_ + seg * 4, ok);
        }
        const float* Bb = WT + ((size_t)tap * Cout + co0) * C_ + kt * 16;
#pragma unroll
        for (int it = 0; it < 2; it++) {
            int chunk = it * 256 + tid;
            int row = chunk >> 2, seg = chunk & 3;
            cp16(sbase + TILE_U32 * 4 + (row * LDK + seg * 4) * 4,
                 Bb + (size_t)row * C_ + seg * 4, 16);
        }
    };

    // prologue: tiles 0..2
    load_tile(0, 0); CP_COMMIT();
    load_tile(1, 1); CP_COMMIT();
    load_tile(2, 2); CP_COMMIT();

    for (int t = 0; t < NT; t++) {
        CP_WAIT2();                 // tile t arrived
        __syncthreads();            // visible to all; stage (t-1)%4 free for reuse
        if (t + 3 < NT) load_tile(t + 3, (t + 3) & 3);
        CP_COMMIT();

        const uint32_t* Ac = sh + (t & 3) * STAGE_U32;
        const uint32_t* Bc = Ac + TILE_U32;
#pragma unroll
        for (int ks = 0; ks < 2; ks++) {
            const int k0 = ks * 8;
            uint32_t af[4][4], bf[4][2];
#pragma unroll
            for (int i = 0; i < 4; i++) {
                const uint32_t* p = Ac + (m0 + i * 16 + r) * LDK + k0 + cq;
                af[i][0] = p[0];
                af[i][1] = p[8 * LDK];
                af[i][2] = p[4];
                af[i][3] = p[8 * LDK + 4];
            }
#pragma unroll
            for (int j = 0; j < 4; j++) {
                const uint32_t* p = Bc + (n0 + j * 8 + r) * LDK + k0 + cq;
                bf[j][0] = p[0];
                bf[j][1] = p[4];
            }
#pragma unroll
            for (int i = 0; i < 4; i++)
#pragma unroll
                for (int j = 0; j < 4; j++)
                    mma_tf32(acc[i][j][0], acc[i][j][1], acc[i][j][2], acc[i][j][3],
                             af[i][0], af[i][1], af[i][2], af[i][3], bf[j][0], bf[j][1]);
        }
    }

    // epilogue: direct stores (float2), bias fused
#pragma unroll
    for (int j = 0; j < 4; j++) {
        const int col = co0 + n0 + j * 8 + 2 * cq;
        const float bv0 = bias[col], bv1 = bias[col + 1];
#pragma unroll
        for (int i = 0; i < 4; i++) {
            int row = t0 + m0 + i * 16 + r;
            float2 v0 = make_float2(acc[i][j][0] + bv0, acc[i][j][1] + bv1);
            float2 v1 = make_float2(acc[i][j][2] + bv0, acc[i][j][3] + bv1);
            *(float2*)(Out + ((size_t)bb * T_ + row) * Cout + col) = v0;
            *(float2*)(Out + ((size_t)bb * T_ + row + 8) * Cout + col) = v1;
        }
    }
}

// ---------------- LayerNorm over time + leaky relu + mask (tf32-rounded out) ----------------
__global__ void ln_lrelu_kernel(float* __restrict__ h,
                                const float* __restrict__ scale,
                                const float* __restrict__ bias,
                                const unsigned char* __restrict__ m) {
    const int b = blockIdx.x;
    const int c = blockIdx.y * 128 + threadIdx.x;
    float* hb = h + (size_t)b * T_ * C_ + c;
    float s = 0.f, s2 = 0.f;
#pragma unroll 8
    for (int t = 0; t < T_; t++) {
        float v = hb[(size_t)t * C_];
        s += v; s2 += v * v;
    }
    const float mu = s * (1.f / T_);
    const float var = s2 * (1.f / T_) - mu * mu;
    const float rs = rsqrtf(var + 1e-5f);
    const unsigned char* mb = m + (size_t)b * T_;
#pragma unroll 4
    for (int t = 0; t < T_; t++) {
        float v = hb[(size_t)t * C_];
        v = (v - mu) * rs * scale[t] + bias[t];
        v = (v > 0.f) ? v : 0.2f * v;
        if (mb[t]) v = 0.f;
        hb[(size_t)t * C_] = tf32r(v);
    }
}

// ---------------- flag reset ----------------
__global__ void reset_flags_kernel() {
    if (threadIdx.x < 128) g_flags[threadIdx.x] = 0;
}

// ---------------- bidirectional LSTM recurrence (register-resident W) ----------------
// Grid 128 CTAs = dir(2) x bg(8: 4 batches) x hg(8: 32 units). 512 threads.
// Thread (g = tid&127 gate-col, kq = tid>>7 k-quarter): holds wh[kq*64..+64][col] in regs.
// Per step: partial dot over its k-quarter for 4 batches; 4-way smem reduce; thread
// (g, bl) applies activation; 128 threads do the cell update; L2 flag exchange.
__global__ __launch_bounds__(512) void lstm_kernel(const float* __restrict__ wh_fw,
                                                   const float* __restrict__ wh_bw) {
    __shared__ float hps[1024];          // [4 batch][256]
    __shared__ float part[4 * 128 * 4];  // [kq][g][bl]
    __shared__ float gbuf[512];          // [g][bl]
    __shared__ float cbuf[128];          // [bl][32]

    const int tid = threadIdx.x;
    const int dir = blockIdx.x >> 6;
    const int bg = (blockIdx.x >> 3) & 7;
    const int hg = blockIdx.x & 7;
    const int u0 = hg * 32;
    const int b0 = bg * 4;

    const int g = tid & 127;
    const int kq = tid >> 7;
    const int q = g >> 5;
    const int j = g & 31;
    const int col = q * 256 + u0 + j;

    // load this thread's wh slice into registers (coalesced per k)
    const float* wh = dir ? wh_bw : wh_fw;
    float wreg[64];
#pragma unroll
    for (int k2 = 0; k2 < 64; k2++)
        wreg[k2] = wh[(size_t)(kq * 64 + k2) * 1024 + col];

    for (int i = tid; i < 1024; i += 512) hps[i] = 0.f;
    if (tid < 128) cbuf[tid] = 0.f;
    __syncthreads();

    const float* xgd = g_xg + (size_t)dir * B_ * T_ * 1024;
    float* hsd = g_hs + (size_t)dir * T_ * B_ * H_;
    volatile unsigned int* flg = (volatile unsigned int*)(g_flags + dir * 64 + bg * 8);

    for (int s = 0; s < T_; s++) {
        const int t = dir ? (T_ - 1 - s) : s;
        // xv for this thread's reduce identity (g, bl=kq)
        float xv = xgd[((size_t)(b0 + kq) * T_ + t) * 1024 + col];

        if (s > 0) {
            if (tid < 8) {
                while (flg[tid] < (unsigned)s) { }
            }
            __syncthreads();
            const int tprev = dir ? (t + 1) : (t - 1);
            const float2* src = (const float2*)(hsd + ((size_t)tprev * B_ + b0) * H_);
            ((float2*)hps)[tid] = __ldcg(src + tid);
        }
        __syncthreads();

        // partial dot products over this thread's k-quarter, all 4 batches
        float acc0 = 0.f, acc1 = 0.f, acc2 = 0.f, acc3 = 0.f;
        const float* hq = hps + kq * 64;
#pragma unroll
        for (int k2 = 0; k2 < 64; k2 += 4) {
            float4 ha = *(const float4*)(hq + k2);
            float4 hb = *(const float4*)(hq + 256 + k2);
            float4 hc = *(const float4*)(hq + 512 + k2);
            float4 hd = *(const float4*)(hq + 768 + k2);
            float w0 = wreg[k2], w1 = wreg[k2 + 1], w2 = wreg[k2 + 2], w3 = wreg[k2 + 3];
            acc0 += w0 * ha.x; acc0 += w1 * ha.y; acc0 += w2 * ha.z; acc0 += w3 * ha.w;
            acc1 += w0 * hb.x; acc1 += w1 * hb.y; acc1 += w2 * hb.z; acc1 += w3 * hb.w;
            acc2 += w0 * hc.x; acc2 += w1 * hc.y; acc2 += w2 * hc.z; acc2 += w3 * hc.w;
            acc3 += w0 * hd.x; acc3 += w1 * hd.y; acc3 += w2 * hd.z; acc3 += w3 * hd.w;
        }
        *(float4*)&part[(kq * 128 + g) * 4] = make_float4(acc0, acc1, acc2, acc3);
        __syncthreads();

        // reduce 4 quarters + activation: thread -> (g, bl=kq)
        {
            float sum = xv
                + part[(0 * 128 + g) * 4 + kq]
                + part[(1 * 128 + g) * 4 + kq]
                + part[(2 * 128 + g) * 4 + kq]
                + part[(3 * 128 + g) * 4 + kq];
            float a = (q == 2) ? tanhf(sum) : (1.f / (1.f + expf(-sum)));
            gbuf[g * 4 + kq] = a;
        }
        __syncthreads();

        if (tid < 128) {
            const int u = tid & 31;
            const int bi = tid >> 5;
            float iv = gbuf[(u) * 4 + bi];
            float fv = gbuf[(32 + u) * 4 + bi];
            float gv = gbuf[(64 + u) * 4 + bi];
            float ov = gbuf[(96 + u) * 4 + bi];
            float cc = fv * cbuf[bi * 32 + u] + iv * gv;
            cbuf[bi * 32 + u] = cc;
            float hn = ov * tanhf(cc);
            hsd[((size_t)t * B_ + b0 + bi) * H_ + u0 + u] = hn;
            __threadfence();
        }
        __syncthreads();
        if (tid == 0) flg[hg] = (unsigned)(s + 1);
    }
}

// ---------------- output transpose [2][T][B][H] -> [B, 2H, T] ----------------
__global__ void out_kernel(float* __restrict__ out, const unsigned char* __restrict__ m) {
    const int dir = blockIdx.y >> 3;
    const int h0 = (blockIdx.y & 7) * 32;
    const int t0 = blockIdx.x * 32;
    const int b = blockIdx.z;
    __shared__ float tile[32][33];
    const float* hsd = g_hs + (size_t)dir * T_ * B_ * H_;
    const int tx = threadIdx.x, ty = threadIdx.y;
#pragma unroll
    for (int r = 0; r < 32; r += 8) {
        int t = t0 + ty + r;
        tile[ty + r][tx] = hsd[((size_t)t * B_ + b) * H_ + h0 + tx];
    }
    __syncthreads();
#pragma unroll
    for (int r = 0; r < 32; r += 8) {
        int hh = ty + r;
        int c = dir * H_ + h0 + hh;
        int t = t0 + tx;
        float v = tile[tx][hh];
        if (m[(size_t)b * T_ + t]) v = 0.f;
        out[((size_t)b * C_ + c) * T_ + t] = v;
    }
}

// ---------------- launch ----------------
extern "C" void kernel_launch(void* const* d_in, const int* in_sizes, int n_in,
                              void* d_out, int out_size) {
    const int* x = (const int*)d_in[0];
    const unsigned char* m = (const unsigned char*)d_in[2];
    const float* emb = (const float*)d_in[3];
    const float* conv_w = (const float*)d_in[4];
    const float* conv_b = (const float*)d_in[5];
    const float* ln_scale = (const float*)d_in[6];
    const float* ln_bias = (const float*)d_in[7];
    const float* wx_fw = (const float*)d_in[8];
    const float* wh_fw = (const float*)d_in[9];
    const float* b_fw = (const float*)d_in[10];
    const float* wx_bw = (const float*)d_in[11];
    const float* wh_bw = (const float*)d_in[12];
    const float* b_bw = (const float*)d_in[13];
    float* out = (float*)d_out;

    float *bufA, *bufB, *xg, *wT, *wxT;
    cudaGetSymbolAddress((void**)&bufA, g_bufA);
    cudaGetSymbolAddress((void**)&bufB, g_bufB);
    cudaGetSymbolAddress((void**)&xg, g_xg);
    cudaGetSymbolAddress((void**)&wT, g_wT);
    cudaGetSymbolAddress((void**)&wxT, g_wxT);

    // 0) weight prep: transpose to K-major + tf32 RNA round
    transpose_round_kernel<<<dim3(16, 16, 15), dim3(32, 8)>>>(conv_w, wT, 512, 512);
    transpose_round_kernel<<<dim3(32, 16, 1), dim3(32, 8)>>>(wx_fw, wxT, 512, 1024);
    transpose_round_kernel<<<dim3(32, 16, 1), dim3(32, 8)>>>(wx_bw, wxT + (size_t)1024 * 512, 512, 1024);

    // 1) embedding (tf32-rounded)
    embed_kernel<<<(int)(((size_t)B_ * T_ * C_) / 256), 256>>>(x, m, emb);

    // 2) conv stack via tf32 mma.sync implicit GEMM (4-stage pipeline)
    cudaFuncSetAttribute(mma_gemm_kernel<5>, cudaFuncAttributeMaxDynamicSharedMemorySize, GEMM_SMEM);
    cudaFuncSetAttribute(mma_gemm_kernel<1>, cudaFuncAttributeMaxDynamicSharedMemorySize, GEMM_SMEM);

    float* cur = bufA;
    float* nxt = bufB;
    for (int d = 0; d < 3; d++) {
        mma_gemm_kernel<5><<<dim3(B_ * 8, 4), 256, GEMM_SMEM>>>(
            cur, wT + (size_t)d * 5 * 512 * 512, conv_b + (size_t)d * 512, nxt, 512);
        ln_lrelu_kernel<<<dim3(B_, 4), 128>>>(nxt, ln_scale + (size_t)d * T_,
                                              ln_bias + (size_t)d * T_, m);
        float* tmp = cur; cur = nxt; nxt = tmp;
    }

    // 3) LSTM input projections (bias fused)
    mma_gemm_kernel<1><<<dim3(B_ * 8, 8), 256, GEMM_SMEM>>>(cur, wxT, b_fw, xg, 1024);
    mma_gemm_kernel<1><<<dim3(B_ * 8, 8), 256, GEMM_SMEM>>>(
        cur, wxT + (size_t)1024 * 512, b_bw, xg + (size_t)B_ * T_ * 1024, 1024);

    // 4) recurrence (register-resident W)
    reset_flags_kernel<<<1, 128>>>();
    lstm_kernel<<<128, 512>>>(wh_fw, wh_bw);

    // 5) concat + transpose + mask -> d_out [B, C, T]
    out_kernel<<<dim3(T_ / 32, 16, B_), dim3(32, 8)>>>(out, m);
}

// round 5
// speedup vs baseline: 2.8165x; 1.2005x over previous
#include <cuda_runtime.h>
#include <cuda_fp16.h>
#include <math.h>
#include <stdint.h>

#define B_ 32
#define T_ 1024
#define C_ 512
#define H_ 256

// ---------------- static device scratch ----------------
__device__ float g_bufA[(size_t)B_ * T_ * C_];                 // fp32 conv output
__device__ __half g_h16[(size_t)B_ * T_ * C_];                 // fp16 GEMM input acts
__device__ float g_xg[(size_t)2 * B_ * T_ * 4 * H_];
__device__ float g_hs[(size_t)2 * T_ * B_ * H_];
__device__ __half g_wT16[(size_t)3 * 5 * 512 * 512];           // conv W [d][tap][co][ci] fp16
__device__ __half g_wxT16[(size_t)2 * 1024 * 512];             // wx [dir][gatecol][ci] fp16
__device__ unsigned int g_flags[128];

// ---------------- helpers ----------------
__device__ __forceinline__ uint32_t smem_u32(const void* p) {
    uint32_t a;
    asm("{ .reg .u64 t; cvta.to.shared.u64 t, %1; cvt.u32.u64 %0, t; }" : "=r"(a) : "l"(p));
    return a;
}
__device__ __forceinline__ void cp16(uint32_t dst, const void* src, int srcsz) {
    asm volatile("cp.async.cg.shared.global [%0], [%1], 16, %2;"
                 :: "r"(dst), "l"(src), "r"(srcsz));
}
#define CP_COMMIT() asm volatile("cp.async.commit_group;")
#define CP_WAIT2()  asm volatile("cp.async.wait_group 2;")

__device__ __forceinline__ void mma_f16(float& c0, float& c1, float& c2, float& c3,
                                        uint32_t a0, uint32_t a1, uint32_t a2, uint32_t a3,
                                        uint32_t b0, uint32_t b1) {
    asm volatile(
        "mma.sync.aligned.m16n8k16.row.col.f32.f16.f16.f32 "
        "{%0,%1,%2,%3}, {%4,%5,%6,%7}, {%8,%9}, {%0,%1,%2,%3};"
        : "+f"(c0), "+f"(c1), "+f"(c2), "+f"(c3)
        : "r"(a0), "r"(a1), "r"(a2), "r"(a3), "r"(b0), "r"(b1));
}

// ---------------- weight transpose -> fp16 ----------------
__global__ void transpose_half_kernel(const float* __restrict__ src, __half* __restrict__ dst,
                                      int R, int Cc) {
    __shared__ float t[32][33];
    const size_t slab = (size_t)R * Cc;
    const float* s = src + (size_t)blockIdx.z * slab;
    __half* d = dst + (size_t)blockIdx.z * slab;
    int c0 = blockIdx.x * 32, r0 = blockIdx.y * 32;
    int x = threadIdx.x, y = threadIdx.y;
#pragma unroll
    for (int i = y; i < 32; i += 8)
        t[i][x] = s[(size_t)(r0 + i) * Cc + c0 + x];
    __syncthreads();
#pragma unroll
    for (int i = y; i < 32; i += 8)
        d[(size_t)(c0 + i) * R + r0 + x] = __float2half(t[x][i]);
}

// ---------------- embedding -> fp16 acts ----------------
__global__ void embed_kernel(const int* __restrict__ x,
                             const unsigned char* __restrict__ m,
                             const float* __restrict__ emb) {
    size_t i = (size_t)blockIdx.x * blockDim.x + threadIdx.x;
    size_t bt = i / C_;
    int c = (int)(i % C_);
    int sym = x[bt];
    float v = emb[(size_t)sym * C_ + c];
    if (m[bt]) v = 0.f;
    g_h16[i] = __float2half(v);
}

// ---------------- fp16 mma.sync GEMM / implicit conv (4-stage, BK=32) ----------------
// Out[b,t,co] = sum_{tap,ci} A16[b,t+tap-half,ci] * WT16[tap,co,ci] + bias[co]
// Block 128x128, BK=32, 256 threads (8 warps 2x4, warp tile 64x32), m16n8k16.
// Smem: [row][k] halves, row stride 40 halves (80B) -> conflict-free frags & stores.
#define LDKH 40
#define TILEH (128 * LDKH)            // halves per operand tile
#define STAGEH (2 * TILEH)            // A + B
#define NSTG 4
#define GEMM_SMEM (NSTG * STAGEH * 2) // bytes (81920)

template <int TAPS>
__global__ __launch_bounds__(256) void mma_gemm_fp16(
    const __half* __restrict__ A,
    const __half* __restrict__ WT, const float* __restrict__ bias, float* __restrict__ Out,
    int Cout,
    const __half* __restrict__ WT2, const float* __restrict__ bias2, float* __restrict__ Out2) {
    extern __shared__ __half shh[];

    if (blockIdx.z) { WT = WT2; bias = bias2; Out = Out2; }

    const int tid = threadIdx.x;
    const int wid = tid >> 5, lane = tid & 31;
    const int r = lane >> 2, cq = lane & 3;
    const int warp_m = wid & 1, warp_n = wid >> 1;
    const int m0 = warp_m * 64, n0 = warp_n * 32;

    const int bb = blockIdx.x >> 3;
    const int t0 = (blockIdx.x & 7) * 128;
    const int co0 = blockIdx.y * 128;
    const int NT = TAPS * 16;             // K tiles of 32
    const int half = (TAPS - 1) / 2;

    float acc[4][4][4];
#pragma unroll
    for (int i = 0; i < 4; i++)
#pragma unroll
        for (int j = 0; j < 4; j++)
#pragma unroll
            for (int k = 0; k < 4; k++) acc[i][j][k] = 0.f;

    const uint32_t shb = smem_u32(shh);

    auto load_tile = [&](int tidx, int stage) {
        const uint32_t sbase = shb + stage * (STAGEH * 2);
        const int tap = (TAPS == 1) ? 0 : (tidx >> 4);
        const int kt = (TAPS == 1) ? tidx : (tidx & 15);
        const __half* Ab = A + (size_t)bb * T_ * C_ + kt * 32;
#pragma unroll
        for (int it = 0; it < 2; it++) {
            int chunk = it * 256 + tid;
            int row = chunk >> 2, seg = chunk & 3;       // seg: 8-half (16B) chunk
            int t = t0 + row + tap - half;
            int ok = ((unsigned)t < (unsigned)T_) ? 16 : 0;
            int tc = t < 0 ? 0 : (t > T_ - 1 ? T_ - 1 : t);
            cp16(sbase + (row * LDKH + seg * 8) * 2, Ab + (size_t)tc * C_ + seg * 8, ok);
        }
        const __half* Bb = WT + ((size_t)tap * Cout + co0) * C_ + kt * 32;
#pragma unroll
        for (int it = 0; it < 2; it++) {
            int chunk = it * 256 + tid;
            int row = chunk >> 2, seg = chunk & 3;
            cp16(sbase + TILEH * 2 + (row * LDKH + seg * 8) * 2,
                 Bb + (size_t)row * C_ + seg * 8, 16);
        }
    };

    // prologue: tiles 0..2
    load_tile(0, 0); CP_COMMIT();
    load_tile(1, 1); CP_COMMIT();
    load_tile(2, 2); CP_COMMIT();

    for (int t = 0; t < NT; t++) {
        CP_WAIT2();
        __syncthreads();
        if (t + 3 < NT) load_tile(t + 3, (t + 3) & 3);
        CP_COMMIT();

        const __half* Ac = shh + (t & 3) * STAGEH;
        const __half* Bc = Ac + TILEH;
#pragma unroll
        for (int ks = 0; ks < 2; ks++) {
            const int k0 = ks * 16;
            uint32_t af[4][4], bf[4][2];
#pragma unroll
            for (int i = 0; i < 4; i++) {
                const __half* p = Ac + (m0 + i * 16 + r) * LDKH + k0 + 2 * cq;
                af[i][0] = *(const uint32_t*)(p);
                af[i][1] = *(const uint32_t*)(p + 8 * LDKH);
                af[i][2] = *(const uint32_t*)(p + 8);
                af[i][3] = *(const uint32_t*)(p + 8 * LDKH + 8);
            }
#pragma unroll
            for (int j = 0; j < 4; j++) {
                const __half* p = Bc + (n0 + j * 8 + r) * LDKH + k0 + 2 * cq;
                bf[j][0] = *(const uint32_t*)(p);
                bf[j][1] = *(const uint32_t*)(p + 8);
            }
#pragma unroll
            for (int i = 0; i < 4; i++)
#pragma unroll
                for (int j = 0; j < 4; j++)
                    mma_f16(acc[i][j][0], acc[i][j][1], acc[i][j][2], acc[i][j][3],
                            af[i][0], af[i][1], af[i][2], af[i][3], bf[j][0], bf[j][1]);
        }
    }

    // epilogue: direct stores (float2), bias fused
#pragma unroll
    for (int j = 0; j < 4; j++) {
        const int col = co0 + n0 + j * 8 + 2 * cq;
        const float bv0 = bias[col], bv1 = bias[col + 1];
#pragma unroll
        for (int i = 0; i < 4; i++) {
            int row = t0 + m0 + i * 16 + r;
            float2 v0 = make_float2(acc[i][j][0] + bv0, acc[i][j][1] + bv1);
            float2 v1 = make_float2(acc[i][j][2] + bv0, acc[i][j][3] + bv1);
            *(float2*)(Out + ((size_t)bb * T_ + row) * Cout + col) = v0;
            *(float2*)(Out + ((size_t)bb * T_ + row + 8) * Cout + col) = v1;
        }
    }
}

// ---------------- LayerNorm over time + leaky relu + mask -> fp16 acts ----------------
__global__ void ln_lrelu_kernel(const float* __restrict__ h, __half* __restrict__ o16,
                                const float* __restrict__ scale,
                                const float* __restrict__ bias,
                                const unsigned char* __restrict__ m) {
    const int b = blockIdx.x;
    const int c = blockIdx.y * 128 + threadIdx.x;
    const float* hb = h + (size_t)b * T_ * C_ + c;
    __half* ob = o16 + (size_t)b * T_ * C_ + c;
    float s = 0.f, s2 = 0.f;
#pragma unroll 8
    for (int t = 0; t < T_; t++) {
        float v = hb[(size_t)t * C_];
        s += v; s2 += v * v;
    }
    const float mu = s * (1.f / T_);
    const float var = s2 * (1.f / T_) - mu * mu;
    const float rs = rsqrtf(var + 1e-5f);
    const unsigned char* mb = m + (size_t)b * T_;
#pragma unroll 4
    for (int t = 0; t < T_; t++) {
        float v = hb[(size_t)t * C_];
        v = (v - mu) * rs * scale[t] + bias[t];
        v = (v > 0.f) ? v : 0.2f * v;
        if (mb[t]) v = 0.f;
        ob[(size_t)t * C_] = __float2half(v);
    }
}

// ---------------- flag reset ----------------
__global__ void reset_flags_kernel() {
    if (threadIdx.x < 128) g_flags[threadIdx.x] = 0;
}

// ---------------- bidirectional LSTM recurrence (register-resident W, fp32) ----------------
__global__ __launch_bounds__(512) void lstm_kernel(const float* __restrict__ wh_fw,
                                                   const float* __restrict__ wh_bw) {
    __shared__ float hps[1024];          // [4 batch][256]
    __shared__ float part[4 * 128 * 4];  // [kq][g][bl]
    __shared__ float gbuf[512];          // [g][bl]
    __shared__ float cbuf[128];          // [bl][32]

    const int tid = threadIdx.x;
    const int dir = blockIdx.x >> 6;
    const int bg = (blockIdx.x >> 3) & 7;
    const int hg = blockIdx.x & 7;
    const int u0 = hg * 32;
    const int b0 = bg * 4;

    const int g = tid & 127;
    const int kq = tid >> 7;
    const int q = g >> 5;
    const int j = g & 31;
    const int col = q * 256 + u0 + j;

    const float* wh = dir ? wh_bw : wh_fw;
    float wreg[64];
#pragma unroll
    for (int k2 = 0; k2 < 64; k2++)
        wreg[k2] = wh[(size_t)(kq * 64 + k2) * 1024 + col];

    for (int i = tid; i < 1024; i += 512) hps[i] = 0.f;
    if (tid < 128) cbuf[tid] = 0.f;
    __syncthreads();

    const float* xgd = g_xg + (size_t)dir * B_ * T_ * 1024;
    float* hsd = g_hs + (size_t)dir * T_ * B_ * H_;
    volatile unsigned int* flg = (volatile unsigned int*)(g_flags + dir * 64 + bg * 8);

    for (int s = 0; s < T_; s++) {
        const int t = dir ? (T_ - 1 - s) : s;
        float xv = xgd[((size_t)(b0 + kq) * T_ + t) * 1024 + col];

        if (s > 0) {
            if (tid < 8) {
                while (flg[tid] < (unsigned)s) { }
            }
            __syncthreads();
            const int tprev = dir ? (t + 1) : (t - 1);
            const float2* src = (const float2*)(hsd + ((size_t)tprev * B_ + b0) * H_);
            ((float2*)hps)[tid] = __ldcg(src + tid);
        }
        __syncthreads();

        float acc0 = 0.f, acc1 = 0.f, acc2 = 0.f, acc3 = 0.f;
        const float* hq = hps + kq * 64;
#pragma unroll
        for (int k2 = 0; k2 < 64; k2 += 4) {
            float4 ha = *(const float4*)(hq + k2);
            float4 hb = *(const float4*)(hq + 256 + k2);
            float4 hc = *(const float4*)(hq + 512 + k2);
            float4 hd = *(const float4*)(hq + 768 + k2);
            float w0 = wreg[k2], w1 = wreg[k2 + 1], w2 = wreg[k2 + 2], w3 = wreg[k2 + 3];
            acc0 += w0 * ha.x; acc0 += w1 * ha.y; acc0 += w2 * ha.z; acc0 += w3 * ha.w;
            acc1 += w0 * hb.x; acc1 += w1 * hb.y; acc1 += w2 * hb.z; acc1 += w3 * hb.w;
            acc2 += w0 * hc.x; acc2 += w1 * hc.y; acc2 += w2 * hc.z; acc2 += w3 * hc.w;
            acc3 += w0 * hd.x; acc3 += w1 * hd.y; acc3 += w2 * hd.z; acc3 += w3 * hd.w;
        }
        *(float4*)&part[(kq * 128 + g) * 4] = make_float4(acc0, acc1, acc2, acc3);
        __syncthreads();

        {
            float sum = xv
                + part[(0 * 128 + g) * 4 + kq]
                + part[(1 * 128 + g) * 4 + kq]
                + part[(2 * 128 + g) * 4 + kq]
                + part[(3 * 128 + g) * 4 + kq];
            float a = (q == 2) ? tanhf(sum) : (1.f / (1.f + expf(-sum)));
            gbuf[g * 4 + kq] = a;
        }
        __syncthreads();

        if (tid < 128) {
            const int u = tid & 31;
            const int bi = tid >> 5;
            float iv = gbuf[(u) * 4 + bi];
            float fv = gbuf[(32 + u) * 4 + bi];
            float gv = gbuf[(64 + u) * 4 + bi];
            float ov = gbuf[(96 + u) * 4 + bi];
            float cc = fv * cbuf[bi * 32 + u] + iv * gv;
            cbuf[bi * 32 + u] = cc;
            float hn = ov * tanhf(cc);
            hsd[((size_t)t * B_ + b0 + bi) * H_ + u0 + u] = hn;
            __threadfence();
        }
        __syncthreads();
        if (tid == 0) flg[hg] = (unsigned)(s + 1);
    }
}

// ---------------- output transpose [2][T][B][H] -> [B, 2H, T] ----------------
__global__ void out_kernel(float* __restrict__ out, const unsigned char* __restrict__ m) {
    const int dir = blockIdx.y >> 3;
    const int h0 = (blockIdx.y & 7) * 32;
    const int t0 = blockIdx.x * 32;
    const int b = blockIdx.z;
    __shared__ float tile[32][33];
    const float* hsd = g_hs + (size_t)dir * T_ * B_ * H_;
    const int tx = threadIdx.x, ty = threadIdx.y;
#pragma unroll
    for (int r = 0; r < 32; r += 8) {
        int t = t0 + ty + r;
        tile[ty + r][tx] = hsd[((size_t)t * B_ + b) * H_ + h0 + tx];
    }
    __syncthreads();
#pragma unroll
    for (int r = 0; r < 32; r += 8) {
        int hh = ty + r;
        int c = dir * H_ + h0 + hh;
        int t = t0 + tx;
        float v = tile[tx][hh];
        if (m[(size_t)b * T_ + t]) v = 0.f;
        out[((size_t)b * C_ + c) * T_ + t] = v;
    }
}

// ---------------- launch ----------------
extern "C" void kernel_launch(void* const* d_in, const int* in_sizes, int n_in,
                              void* d_out, int out_size) {
    const int* x = (const int*)d_in[0];
    const unsigned char* m = (const unsigned char*)d_in[2];
    const float* emb = (const float*)d_in[3];
    const float* conv_w = (const float*)d_in[4];
    const float* conv_b = (const float*)d_in[5];
    const float* ln_scale = (const float*)d_in[6];
    const float* ln_bias = (const float*)d_in[7];
    const float* wx_fw = (const float*)d_in[8];
    const float* wh_fw = (const float*)d_in[9];
    const float* b_fw = (const float*)d_in[10];
    const float* wx_bw = (const float*)d_in[11];
    const float* wh_bw = (const float*)d_in[12];
    const float* b_bw = (const float*)d_in[13];
    float* out = (float*)d_out;

    float *bufA, *xg;
    __half *h16, *wT16, *wxT16;
    cudaGetSymbolAddress((void**)&bufA, g_bufA);
    cudaGetSymbolAddress((void**)&xg, g_xg);
    cudaGetSymbolAddress((void**)&h16, g_h16);
    cudaGetSymbolAddress((void**)&wT16, g_wT16);
    cudaGetSymbolAddress((void**)&wxT16, g_wxT16);

    // 0) weight prep: transpose to K-major + fp16
    transpose_half_kernel<<<dim3(16, 16, 15), dim3(32, 8)>>>(conv_w, wT16, 512, 512);
    transpose_half_kernel<<<dim3(32, 16, 1), dim3(32, 8)>>>(wx_fw, wxT16, 512, 1024);
    transpose_half_kernel<<<dim3(32, 16, 1), dim3(32, 8)>>>(wx_bw, wxT16 + (size_t)1024 * 512, 512, 1024);

    // 1) embedding -> fp16 acts
    embed_kernel<<<(int)(((size_t)B_ * T_ * C_) / 256), 256>>>(x, m, emb);

    // 2) conv stack via fp16 mma.sync implicit GEMM
    cudaFuncSetAttribute(mma_gemm_fp16<5>, cudaFuncAttributeMaxDynamicSharedMemorySize, GEMM_SMEM);
    cudaFuncSetAttribute(mma_gemm_fp16<1>, cudaFuncAttributeMaxDynamicSharedMemorySize, GEMM_SMEM);

    for (int d = 0; d < 3; d++) {
        mma_gemm_fp16<5><<<dim3(B_ * 8, 4, 1), 256, GEMM_SMEM>>>(
            h16, wT16 + (size_t)d * 5 * 512 * 512, conv_b + (size_t)d * 512, bufA, 512,
            wT16, conv_b, bufA);
        ln_lrelu_kernel<<<dim3(B_, 4), 128>>>(bufA, h16, ln_scale + (size_t)d * T_,
                                              ln_bias + (size_t)d * T_, m);
    }

    // 3) LSTM input projections (fw + bw in one launch, bias fused)
    mma_gemm_fp16<1><<<dim3(B_ * 8, 8, 2), 256, GEMM_SMEM>>>(
        h16, wxT16, b_fw, xg, 1024,
        wxT16 + (size_t)1024 * 512, b_bw, xg + (size_t)B_ * T_ * 1024);

    // 4) recurrence (register-resident W)
    reset_flags_kernel<<<1, 128>>>();
    lstm_kernel<<<128, 512>>>(wh_fw, wh_bw);

    // 5) concat + transpose + mask -> d_out [B, C, T]
    out_kernel<<<dim3(T_ / 32, 16, B_), dim3(32, 8)>>>(out, m);
}